// round 16
// baseline (speedup 1.0000x reference)
#include <cuda_runtime.h>

#define GG 128
#define G3 (GG * GG * GG)
#define NCASC 5
#define MAXCAMS 32
#define C4 24  // float4 per camera constant block

#define NTHREADS 128
#define CELLS_PER_REG 1024u   // 16 x 8 x 8 region (x:4 bits, y:3, z:3)
#define NREG (G3 / (int)CELLS_PER_REG)   // 2048
#define NCTAS (NREG / 2)                 // 1024, single wave, 2 regions each

// Per-cam constants (float4 units) in shared memory, built in-kernel:
// [0] = (M00,M01,M02, rad0t)   thread-level interval radii in .w
// [1] = (M10,M11,M12, rad1t)
// [2] = (M20,M21,M22, rad2t)
// [3] = (rad3t, rad4t, W, H)
// per cascade c (base = 4+4c):
// [base+0] = (A, B, C, D)      exact thresholds (per-cell path)
// [base+1] = (E, F, E_in, F_out)
// [base+2] = (A_in, B_in, C_in, D_in)    thread-level all-in
// [base+3] = (A_out, B_out, C_out, D_out) thread-level all-out

__device__ __forceinline__ unsigned compact3(unsigned x) {
    x &= 0x49249249u;
    x = (x | (x >> 2))  & 0xC30C30C3u;
    x = (x | (x >> 4))  & 0x0F00F00Fu;
    x = (x | (x >> 8))  & 0xFF0000FFu;
    x = (x | (x >> 16)) & 0x000003FFu;
    return x;
}

__global__ void __launch_bounds__(NTHREADS, 8)
grid_kernel(float* __restrict__ out,
            const float* __restrict__ K,
            const float* __restrict__ poses,
            const int* __restrict__ scale_p,
            const int* __restrict__ wp,
            const int* __restrict__ hp,
            int n_cams)
{
    __shared__ float4 s_cc[MAXCAMS * C4];
    __shared__ float3 s_q[MAXCAMS];
    __shared__ float  s_xyz[GG];                  // exact cell coords: i/(G-1)*2-1
    __shared__ float4 s_ctaIn[MAXCAMS * NCASC];   // region-level all-in thresholds
    __shared__ float4 s_ctaOut[MAXCAMS * NCASC];  // region-level all-out thresholds
    __shared__ float2 s_ctaEF[MAXCAMS * NCASC];   // (E_in_region, F_out_region)
    __shared__ int s_allin[2][NCASC];             // double-buffered per region
    __shared__ int s_bnd[2][MAXCAMS];

    const int tid = threadIdx.x;
    // coordinate LUT: identical expression to the reference per-cell math
    s_xyz[tid] = __fdiv_rn((float)tid, (float)(GG - 1)) * 2.0f - 1.0f;
    if (tid < 2 * NCASC) s_allin[tid / NCASC][tid % NCASC] = 0;
    if (tid < 2 * MAXCAMS) s_bnd[tid >> 5][tid & 31] = 0;

    // ---- Phase 1a: per-cam matrix/radii (one thread per cam), ONCE ----
    if (tid < n_cams) {
        const float fx = K[0], cx = K[2], fy = K[4], cy = K[5];
        const float W = (float)(*wp), H = (float)(*hp);

        const float* P = poses + tid * 12;
        const float R00 = P[0], R01 = P[1], R02 = P[2],  t0 = P[3];
        const float R10 = P[4], R11 = P[5], R12 = P[6],  t1 = P[7];
        const float R20 = P[8], R21 = P[9], R22 = P[10], t2 = P[11];
        // T' = -R^T t
        const float Tp0 = -(R00 * t0 + R10 * t1 + R20 * t2);
        const float Tp1 = -(R01 * t0 + R11 * t1 + R21 * t2);
        const float Tp2 = -(R02 * t0 + R12 * t1 + R22 * t2);
        // M = K @ R^T rows
        const float M00 = fx * R00 + cx * R02, M01 = fx * R10 + cx * R12, M02 = fx * R20 + cx * R22;
        const float M10 = fy * R01 + cy * R02, M11 = fy * R11 + cy * R12, M12 = fy * R21 + cy * R22;
        const float M20 = R02, M21 = R12, M22 = R22;
        s_q[tid] = make_float3(fx * Tp0 + cx * Tp2, fy * Tp1 + cy * Tp2, Tp2);

        // thread-level (2x2x2 block) interval radii, conservative
        const float h = 1.0f / (float)(GG - 1);
        const float INFL = 1.001f, EPSA = 0.03f;
        const float rad0 = (fabsf(M00) + fabsf(M01) + fabsf(M02)) * h * INFL + EPSA;
        const float rad1 = (fabsf(M10) + fabsf(M11) + fabsf(M12)) * h * INFL + EPSA;
        const float rad2 = (fabsf(M20) + fabsf(M21) + fabsf(M22)) * h * INFL + EPSA;
        const float rad3 = (fabsf(M00 - W * M20) + fabsf(M01 - W * M21) +
                            fabsf(M02 - W * M22)) * h * INFL + EPSA;
        const float rad4 = (fabsf(M10 - H * M20) + fabsf(M11 - H * M21) +
                            fabsf(M12 - H * M22)) * h * INFL + EPSA;

        float4* cc = s_cc + tid * C4;
        cc[0] = make_float4(M00, M01, M02, rad0);
        cc[1] = make_float4(M10, M11, M12, rad1);
        cc[2] = make_float4(M20, M21, M22, rad2);
        cc[3] = make_float4(rad3, rad4, W, H);
    }
    __syncthreads();

    // ---- Phase 1b: one thread per (cam,cascade): cascade constants +
    //      region-level (16x8x8) classification thresholds, ONCE ----
    const int nPairs = n_cams * NCASC;
    if (tid < nPairs) {
        const int cam = tid / NCASC;
        const int c = tid - cam * NCASC;
        float4* cc = s_cc + cam * C4;
        const float4 m0 = cc[0], m1 = cc[1], m2 = cc[2], m3 = cc[3];
        const float rad0 = m0.w, rad1 = m1.w, rad2 = m2.w;
        const float rad3 = m3.x, rad4 = m3.y, W = m3.z, H = m3.w;
        const float3 q = s_q[cam];
        const float scal = (float)(*scale_p);

        float s = fminf(exp2f((float)(c - 1)), scal);
        float se = s - s * (1.0f / (float)GG);   // exact: powers of two
        float inv = __fdiv_rn(1.0f, se);
        const float A = -q.x * inv;
        const float B = (W * q.z - q.x) * inv;
        const float C = -q.y * inv;
        const float D = (H * q.z - q.y) * inv;
        const float E = (0.01f - q.z) * inv;
        const float F = -q.z * inv;
        cc[4 + 4 * c + 0] = make_float4(A, B, C, D);
        cc[4 + 4 * c + 1] = make_float4(E, F, E + rad2, F - rad2);
        cc[4 + 4 * c + 2] = make_float4(A + rad0, B - rad3, C + rad1, D - rad4);
        cc[4 + 4 * c + 3] = make_float4(A - rad0, B + rad3, C - rad1, D + rad4);

        // region-level radii (region half-extents in normalized coords)
        const float ex = 15.0f / 127.0f, ey = 7.0f / 127.0f, ez = 7.0f / 127.0f;
        const float INFL = 1.001f, EPSA = 0.03f;
        const float Rr0 = (fabsf(m0.x) * ex + fabsf(m0.y) * ey + fabsf(m0.z) * ez) * INFL + EPSA;
        const float Rr1 = (fabsf(m1.x) * ex + fabsf(m1.y) * ey + fabsf(m1.z) * ez) * INFL + EPSA;
        const float Rr2 = (fabsf(m2.x) * ex + fabsf(m2.y) * ey + fabsf(m2.z) * ez) * INFL + EPSA;
        const float g0x = m0.x - W * m2.x, g0y = m0.y - W * m2.y, g0z = m0.z - W * m2.z;
        const float g1x = m1.x - H * m2.x, g1y = m1.y - H * m2.y, g1z = m1.z - H * m2.z;
        const float Rr3 = (fabsf(g0x) * ex + fabsf(g0y) * ey + fabsf(g0z) * ez) * INFL + EPSA;
        const float Rr4 = (fabsf(g1x) * ex + fabsf(g1y) * ey + fabsf(g1z) * ez) * INFL + EPSA;

        s_ctaIn[tid]  = make_float4(A + Rr0, B - Rr3, C + Rr1, D - Rr4);
        s_ctaOut[tid] = make_float4(A - Rr0, B + Rr3, C - Rr1, D + Rr4);
        s_ctaEF[tid]  = make_float2(E + Rr2, F - Rr2);
    }
    __syncthreads();

    // ---- Phase 2: classify BOTH regions (interleaved assignment) ----
    const unsigned regBase[2] = { blockIdx.x * CELLS_PER_REG,
                                  (blockIdx.x + NCTAS) * CELLS_PER_REG };
    for (int i = tid; i < 2 * nPairs; i += NTHREADS) {
        const int r = (i < nPairs) ? 0 : 1;
        const int pair = i - r * nPairs;
        const int cam = pair / NCASC;
        const int c = pair - cam * NCASC;
        const float4* cc = s_cc + cam * C4;
        const float4 m0 = cc[0], m1 = cc[1], m2 = cc[2], m3 = cc[3];
        const float W = m3.z, H = m3.w;

        const unsigned br = regBase[r];
        const unsigned i0 = compact3(br);
        const unsigned j0 = compact3(br >> 1);
        const unsigned k0 = compact3(br >> 2);
        const float inv127 = 2.0f / 127.0f;
        const float xc = ((float)i0 + 7.5f) * inv127 - 1.0f;
        const float yc = ((float)j0 + 3.5f) * inv127 - 1.0f;
        const float zc = ((float)k0 + 3.5f) * inv127 - 1.0f;

        const float p0 = m0.x * xc + m0.y * yc + m0.z * zc;
        const float p1 = m1.x * xc + m1.y * yc + m1.z * zc;
        const float p2 = m2.x * xc + m2.y * yc + m2.z * zc;
        const float r0 = p0 - W * p2;
        const float r1 = p1 - H * p2;

        const float4 vin  = s_ctaIn[pair];
        const float4 vout = s_ctaOut[pair];
        const float2 vef  = s_ctaEF[pair];
        bool allin  = (p0 >= vin.x) & (r0 < vin.y) & (p1 >= vin.z) &
                      (r1 < vin.w) & (p2 >= vef.x);
        bool allout = (p0 < vout.x) | (r0 >= vout.y) | (p1 < vout.z) |
                      (r1 >= vout.w) | (p2 <= vef.y);
        if (allin) atomicAdd(&s_allin[r][c], 1);
        else if (!allout) atomicOr(&s_bnd[r][cam], 1 << c);
    }
    __syncthreads();   // LAST barrier: both buffers final from here on

    const float invN = __fdiv_rn(1.0f, (float)n_cams);
    const float W = s_cc[3].z, H = s_cc[3].w;

    // ---- Phases 3+4 for each owned region, no further barriers ----
#pragma unroll
    for (int r = 0; r < 2; r++) {
        const unsigned base = regBase[r] + (unsigned)tid * 8u;
        const unsigned ib = compact3(base);
        const unsigned jb = compact3(base >> 1);
        const unsigned kb = compact3(base >> 2);

        float xs[2], ys[2], zs[2];
#pragma unroll
        for (int d = 0; d < 2; d++) {
            xs[d] = s_xyz[ib + d];
            ys[d] = s_xyz[jb + d];
            zs[d] = s_xyz[kb + d];
        }
        const float xc = 0.5f * (xs[0] + xs[1]);
        const float yc = 0.5f * (ys[0] + ys[1]);
        const float zc = 0.5f * (zs[0] + zs[1]);

        // build per-thread presence mask of boundary cams from 8 LDS.128
        unsigned camMask = 0u;
        {
            const int4* pb = (const int4*)s_bnd[r];
#pragma unroll
            for (int q4 = 0; q4 < MAXCAMS / 4; q4++) {
                const int4 v = pb[q4];
                if (v.x) camMask |= 1u << (q4 * 4 + 0);
                if (v.y) camMask |= 1u << (q4 * 4 + 1);
                if (v.z) camMask |= 1u << (q4 * 4 + 2);
                if (v.w) camMask |= 1u << (q4 * 4 + 3);
            }
        }

        unsigned acc[8];
#pragma unroll
        for (int i = 0; i < 8; i++) acc[i] = 0u;
        unsigned cntThr = 0u;

        while (camMask) {
            const int cam = __ffs(camMask) - 1;
            camMask &= camMask - 1;
            const unsigned bm = (unsigned)s_bnd[r][cam];
            const float4* c4 = s_cc + cam * C4;
            const float4 m0 = c4[0], m1 = c4[1], m2 = c4[2];

            const float p0 = fmaf(m0.z, zc, fmaf(m0.y, yc, m0.x * xc));
            const float p1 = fmaf(m1.z, zc, fmaf(m1.y, yc, m1.x * xc));
            const float p2 = fmaf(m2.z, zc, fmaf(m2.y, yc, m2.x * xc));
            const float r0 = fmaf(-W, p2, p0);
            const float r1 = fmaf(-H, p2, p1);

#pragma unroll
            for (int c = 0; c < NCASC; c++) {
                if (!((bm >> c) & 1u)) continue;
                const float4 vef  = c4[4 + 4 * c + 1];
                const float4 vin  = c4[4 + 4 * c + 2];
                const float4 vout = c4[4 + 4 * c + 3];
                bool allin  = (p0 >= vin.x) & (r0 < vin.y) & (p1 >= vin.z) &
                              (r1 < vin.w) & (p2 >= vef.z);
                bool allout = (p0 < vout.x) | (r0 >= vout.y) | (p1 < vout.z) |
                              (r1 >= vout.w) | (p2 <= vef.w);
                if (allin) { cntThr += (1u << (5 * c)); continue; }
                if (allout) continue;

                // exact per-cell path (identical math to reference thresholds)
                const float4 v0 = c4[4 + 4 * c + 0];
                const unsigned covbit = 1u << (5 * c);
                const unsigned nearbit = 1u << (25 + c);
#pragma unroll
                for (int cell = 0; cell < 8; cell++) {
                    const float x = xs[cell & 1];
                    const float y = ys[(cell >> 1) & 1];
                    const float z = zs[(cell >> 2) & 1];
                    const float P0 = fmaf(m0.z, z, fmaf(m0.y, y, m0.x * x));
                    const float P1 = fmaf(m1.z, z, fmaf(m1.y, y, m1.x * x));
                    const float P2 = fmaf(m2.z, z, fmaf(m2.y, y, m2.x * x));
                    const float R0 = fmaf(-W, P2, P0);
                    const float R1 = fmaf(-H, P2, P1);
                    bool i4 = (P0 >= v0.x) & (R0 < v0.y) & (P1 >= v0.z) & (R1 < v0.w);
                    if (i4 & (P2 >= vef.x)) acc[cell] += covbit;
                    if (i4 & (P2 < vef.x) & (P2 > vef.y)) acc[cell] |= nearbit;
                }
            }
        }

        // ---- epilogue (incremental pointers) ----
        float* pg = out + base;
        float* pc = out + (size_t)NCASC * G3 + base;

        unsigned any = 0u;
#pragma unroll
        for (int i = 0; i < 8; i++) any |= acc[i];

        if (any == 0u) {
            // uniform fast path: all 8 cells share one value per cascade
#pragma unroll
            for (int c = 0; c < NCASC; c++) {
                const unsigned cnt = (unsigned)s_allin[r][c] + ((cntThr >> (5 * c)) & 31u);
                const float cv = (float)cnt * invN;
                const float gv = (cnt > 0u) ? 0.0f : -1.0f;
                float4 g4 = make_float4(gv, gv, gv, gv);
                float4 c4v = make_float4(cv, cv, cv, cv);
                ((float4*)pg)[0] = g4; ((float4*)pg)[1] = g4;
                ((float4*)pc)[0] = c4v; ((float4*)pc)[1] = c4v;
                pg += G3; pc += G3;
            }
        } else {
#pragma unroll
            for (int c = 0; c < NCASC; c++) {
                const unsigned allc = (unsigned)s_allin[r][c] + ((cntThr >> (5 * c)) & 31u);
                float gv[8], cv[8];
#pragma unroll
                for (int cell = 0; cell < 8; cell++) {
                    unsigned cnt   = ((acc[cell] >> (5 * c)) & 31u) + allc;
                    unsigned nearf = (acc[cell] >> (25 + c)) & 1u;
                    cv[cell] = (float)cnt * invN;
                    gv[cell] = (cnt > 0u && nearf == 0u) ? 0.0f : -1.0f;
                }
                ((float4*)pg)[0] = make_float4(gv[0], gv[1], gv[2], gv[3]);
                ((float4*)pg)[1] = make_float4(gv[4], gv[5], gv[6], gv[7]);
                ((float4*)pc)[0] = make_float4(cv[0], cv[1], cv[2], cv[3]);
                ((float4*)pc)[1] = make_float4(cv[4], cv[5], cv[6], cv[7]);
                pg += G3; pc += G3;
            }
        }
    }
}

extern "C" void kernel_launch(void* const* d_in, const int* in_sizes, int n_in,
                              void* d_out, int out_size)
{
    const float* K     = (const float*)d_in[0];
    const float* poses = (const float*)d_in[1];
    const int*   sc    = (const int*)d_in[3];
    const int*   wp    = (const int*)d_in[4];
    const int*   hp    = (const int*)d_in[5];

    int n_cams = in_sizes[1] / 12;
    if (n_cams > MAXCAMS) n_cams = MAXCAMS;

    grid_kernel<<<NCTAS, NTHREADS>>>((float*)d_out, K, poses, sc, wp, hp, n_cams);
}

// round 17
// speedup vs baseline: 1.1370x; 1.1370x over previous
#include <cuda_runtime.h>

#define GG 128
#define G3 (GG * GG * GG)
#define NCASC 5
#define MAXCAMS 32
#define C4 24  // float4 per camera constant block

#define NTHREADS 128
#define CELLS_PER_CTA 1024u   // 16 x 8 x 8 region (x:4 bits, y:3, z:3)

// Per-cam constants (float4 units) in shared memory, built in-kernel:
// [0] = (M00,M01,M02, rad0t)   thread-level interval radii in .w
// [1] = (M10,M11,M12, rad1t)
// [2] = (M20,M21,M22, rad2t)
// [3] = (rad3t, rad4t, W, H)
// per cascade c (base = 4+4c):
// [base+0] = (A, B, C, D)      exact thresholds (per-cell path)
// [base+1] = (E, F, E_in, F_out)
// [base+2] = (A_in, B_in, C_in, D_in)    thread-level all-in
// [base+3] = (A_out, B_out, C_out, D_out) thread-level all-out

__device__ __forceinline__ unsigned compact3(unsigned x) {
    x &= 0x49249249u;
    x = (x | (x >> 2))  & 0xC30C30C3u;
    x = (x | (x >> 4))  & 0x0F00F00Fu;
    x = (x | (x >> 8))  & 0xFF0000FFu;
    x = (x | (x >> 16)) & 0x000003FFu;
    return x;
}

__global__ void __launch_bounds__(NTHREADS, 8)
grid_kernel(float* __restrict__ out,
            const float* __restrict__ K,
            const float* __restrict__ poses,
            const int* __restrict__ scale_p,
            const int* __restrict__ wp,
            const int* __restrict__ hp,
            int n_cams)
{
    __shared__ float4 s_cc[MAXCAMS * C4];
    __shared__ float3 s_q[MAXCAMS];
    __shared__ float s_xyz[GG];      // exact cell coords: i/(G-1)*2-1
    __shared__ int s_allin[NCASC];
    __shared__ int s_bnd[MAXCAMS];

    const int tid = threadIdx.x;
    if (tid < NCASC) s_allin[tid] = 0;
    if (tid < MAXCAMS) s_bnd[tid] = 0;
    // coordinate LUT: identical expression to the reference per-cell math
    s_xyz[tid] = __fdiv_rn((float)tid, (float)(GG - 1)) * 2.0f - 1.0f;

    // ---- Phase 1a: per-cam matrix/radii (FMA only, one thread per cam) ----
    if (tid < n_cams) {
        const float fx = K[0], cx = K[2], fy = K[4], cy = K[5];
        const float W = (float)(*wp), H = (float)(*hp);

        const float* P = poses + tid * 12;
        const float R00 = P[0], R01 = P[1], R02 = P[2],  t0 = P[3];
        const float R10 = P[4], R11 = P[5], R12 = P[6],  t1 = P[7];
        const float R20 = P[8], R21 = P[9], R22 = P[10], t2 = P[11];
        // T' = -R^T t
        const float Tp0 = -(R00 * t0 + R10 * t1 + R20 * t2);
        const float Tp1 = -(R01 * t0 + R11 * t1 + R21 * t2);
        const float Tp2 = -(R02 * t0 + R12 * t1 + R22 * t2);
        // M = K @ R^T rows
        const float M00 = fx * R00 + cx * R02, M01 = fx * R10 + cx * R12, M02 = fx * R20 + cx * R22;
        const float M10 = fy * R01 + cy * R02, M11 = fy * R11 + cy * R12, M12 = fy * R21 + cy * R22;
        const float M20 = R02, M21 = R12, M22 = R22;
        s_q[tid] = make_float3(fx * Tp0 + cx * Tp2, fy * Tp1 + cy * Tp2, Tp2);

        // thread-level (2x2x2 block) interval radii, conservative
        const float h = 1.0f / (float)(GG - 1);
        const float INFL = 1.001f, EPSA = 0.03f;
        const float rad0 = (fabsf(M00) + fabsf(M01) + fabsf(M02)) * h * INFL + EPSA;
        const float rad1 = (fabsf(M10) + fabsf(M11) + fabsf(M12)) * h * INFL + EPSA;
        const float rad2 = (fabsf(M20) + fabsf(M21) + fabsf(M22)) * h * INFL + EPSA;
        const float rad3 = (fabsf(M00 - W * M20) + fabsf(M01 - W * M21) +
                            fabsf(M02 - W * M22)) * h * INFL + EPSA;
        const float rad4 = (fabsf(M10 - H * M20) + fabsf(M11 - H * M21) +
                            fabsf(M12 - H * M22)) * h * INFL + EPSA;

        float4* cc = s_cc + tid * C4;
        cc[0] = make_float4(M00, M01, M02, rad0);
        cc[1] = make_float4(M10, M11, M12, rad1);
        cc[2] = make_float4(M20, M21, M22, rad2);
        cc[3] = make_float4(rad3, rad4, W, H);
    }
    __syncthreads();

    // ---- Phase 1b+2: one thread per (cam,cascade): build cascade constants
    //      (single FDIV each) AND classify this CTA region against them ----
    const unsigned baseCTA = blockIdx.x * CELLS_PER_CTA;
    if (tid < n_cams * NCASC) {
        const int cam = tid / NCASC;
        const int c = tid - cam * NCASC;
        float4* cc = s_cc + cam * C4;
        const float4 m0 = cc[0], m1 = cc[1], m2 = cc[2], m3 = cc[3];
        const float rad0 = m0.w, rad1 = m1.w, rad2 = m2.w;
        const float rad3 = m3.x, rad4 = m3.y, W = m3.z, H = m3.w;
        const float3 q = s_q[cam];
        const float scal = (float)(*scale_p);

        float s = fminf(exp2f((float)(c - 1)), scal);
        float se = s - s * (1.0f / (float)GG);   // exact: powers of two
        float inv = __fdiv_rn(1.0f, se);
        const float A = -q.x * inv;
        const float B = (W * q.z - q.x) * inv;
        const float C = -q.y * inv;
        const float D = (H * q.z - q.y) * inv;
        const float E = (0.01f - q.z) * inv;
        const float F = -q.z * inv;
        cc[4 + 4 * c + 0] = make_float4(A, B, C, D);
        cc[4 + 4 * c + 1] = make_float4(E, F, E + rad2, F - rad2);
        cc[4 + 4 * c + 2] = make_float4(A + rad0, B - rad3, C + rad1, D - rad4);
        cc[4 + 4 * c + 3] = make_float4(A - rad0, B + rad3, C - rad1, D + rad4);

        // CTA-level classification (region = 16x8x8 cells), thresholds in regs
        const unsigned i0 = compact3(baseCTA);
        const unsigned j0 = compact3(baseCTA >> 1);
        const unsigned k0 = compact3(baseCTA >> 2);
        const float inv127 = 2.0f / 127.0f;
        const float xc = ((float)i0 + 7.5f) * inv127 - 1.0f;
        const float yc = ((float)j0 + 3.5f) * inv127 - 1.0f;
        const float zc = ((float)k0 + 3.5f) * inv127 - 1.0f;
        const float ex = 15.0f / 127.0f, ey = 7.0f / 127.0f, ez = 7.0f / 127.0f;

        const float p0 = m0.x * xc + m0.y * yc + m0.z * zc;
        const float p1 = m1.x * xc + m1.y * yc + m1.z * zc;
        const float p2 = m2.x * xc + m2.y * yc + m2.z * zc;
        const float r0 = p0 - W * p2;
        const float r1 = p1 - H * p2;

        const float INFL = 1.001f, EPSA = 0.03f;
        const float Rr0 = (fabsf(m0.x) * ex + fabsf(m0.y) * ey + fabsf(m0.z) * ez) * INFL + EPSA;
        const float Rr1 = (fabsf(m1.x) * ex + fabsf(m1.y) * ey + fabsf(m1.z) * ez) * INFL + EPSA;
        const float Rr2 = (fabsf(m2.x) * ex + fabsf(m2.y) * ey + fabsf(m2.z) * ez) * INFL + EPSA;
        const float g0x = m0.x - W * m2.x, g0y = m0.y - W * m2.y, g0z = m0.z - W * m2.z;
        const float g1x = m1.x - H * m2.x, g1y = m1.y - H * m2.y, g1z = m1.z - H * m2.z;
        const float Rr3 = (fabsf(g0x) * ex + fabsf(g0y) * ey + fabsf(g0z) * ez) * INFL + EPSA;
        const float Rr4 = (fabsf(g1x) * ex + fabsf(g1y) * ey + fabsf(g1z) * ez) * INFL + EPSA;

        bool allin  = (p0 >= A + Rr0) & (r0 < B - Rr3) & (p1 >= C + Rr1) &
                      (r1 < D - Rr4) & (p2 >= E + Rr2);
        bool allout = (p0 < A - Rr0) | (r0 >= B + Rr3) | (p1 < C - Rr1) |
                      (r1 >= D + Rr4) | (p2 <= F - Rr2);
        if (allin) atomicAdd(&s_allin[c], 1);
        else if (!allout) atomicOr(&s_bnd[cam], 1 << c);
    }
    __syncthreads();   // LAST barrier

    // ---- Phase 3: per-thread (2x2x2) processing of CTA-boundary cams ----
    const unsigned base = baseCTA + (unsigned)tid * 8u;
    const unsigned ib = compact3(base);
    const unsigned jb = compact3(base >> 1);
    const unsigned kb = compact3(base >> 2);

    float xs[2], ys[2], zs[2];
#pragma unroll
    for (int d = 0; d < 2; d++) {
        xs[d] = s_xyz[ib + d];
        ys[d] = s_xyz[jb + d];
        zs[d] = s_xyz[kb + d];
    }
    const float xc = 0.5f * (xs[0] + xs[1]);
    const float yc = 0.5f * (ys[0] + ys[1]);
    const float zc = 0.5f * (zs[0] + zs[1]);
    const float W = s_cc[3].z, H = s_cc[3].w;

    // per-thread presence mask of boundary cams (8 x LDS.128, no barrier/ballot)
    unsigned camMask = 0u;
    {
        const int4* pb = (const int4*)s_bnd;
#pragma unroll
        for (int q4 = 0; q4 < MAXCAMS / 4; q4++) {
            const int4 v = pb[q4];
            if (v.x) camMask |= 1u << (q4 * 4 + 0);
            if (v.y) camMask |= 1u << (q4 * 4 + 1);
            if (v.z) camMask |= 1u << (q4 * 4 + 2);
            if (v.w) camMask |= 1u << (q4 * 4 + 3);
        }
    }

    unsigned acc[8];
#pragma unroll
    for (int i = 0; i < 8; i++) acc[i] = 0u;
    unsigned cntThr = 0u;

    while (camMask) {
        const int cam = __ffs(camMask) - 1;
        camMask &= camMask - 1;
        const unsigned bm = (unsigned)s_bnd[cam];
        const float4* c4 = s_cc + cam * C4;
        const float4 m0 = c4[0], m1 = c4[1], m2 = c4[2];

        const float p0 = fmaf(m0.z, zc, fmaf(m0.y, yc, m0.x * xc));
        const float p1 = fmaf(m1.z, zc, fmaf(m1.y, yc, m1.x * xc));
        const float p2 = fmaf(m2.z, zc, fmaf(m2.y, yc, m2.x * xc));
        const float r0 = fmaf(-W, p2, p0);
        const float r1 = fmaf(-H, p2, p1);

#pragma unroll
        for (int c = 0; c < NCASC; c++) {
            if (!((bm >> c) & 1u)) continue;
            const float4 vef  = c4[4 + 4 * c + 1];
            const float4 vin  = c4[4 + 4 * c + 2];
            const float4 vout = c4[4 + 4 * c + 3];
            bool allin  = (p0 >= vin.x) & (r0 < vin.y) & (p1 >= vin.z) &
                          (r1 < vin.w) & (p2 >= vef.z);
            bool allout = (p0 < vout.x) | (r0 >= vout.y) | (p1 < vout.z) |
                          (r1 >= vout.w) | (p2 <= vef.w);
            if (allin) { cntThr += (1u << (5 * c)); continue; }
            if (allout) continue;

            // exact per-cell path (identical math to reference thresholds)
            const float4 v0 = c4[4 + 4 * c + 0];
            const unsigned covbit = 1u << (5 * c);
            const unsigned nearbit = 1u << (25 + c);
#pragma unroll
            for (int cell = 0; cell < 8; cell++) {
                const float x = xs[cell & 1];
                const float y = ys[(cell >> 1) & 1];
                const float z = zs[(cell >> 2) & 1];
                const float P0 = fmaf(m0.z, z, fmaf(m0.y, y, m0.x * x));
                const float P1 = fmaf(m1.z, z, fmaf(m1.y, y, m1.x * x));
                const float P2 = fmaf(m2.z, z, fmaf(m2.y, y, m2.x * x));
                const float R0 = fmaf(-W, P2, P0);
                const float R1 = fmaf(-H, P2, P1);
                bool i4 = (P0 >= v0.x) & (R0 < v0.y) & (P1 >= v0.z) & (R1 < v0.w);
                if (i4 & (P2 >= vef.x)) acc[cell] += covbit;
                if (i4 & (P2 < vef.x) & (P2 > vef.y)) acc[cell] |= nearbit;
            }
        }
    }

    // ---- Phase 4: epilogue (incremental pointers) ----
    const float invN = __fdiv_rn(1.0f, (float)n_cams);
    float* pg = out + base;
    float* pc = out + (size_t)NCASC * G3 + base;

    unsigned any = 0u;
#pragma unroll
    for (int i = 0; i < 8; i++) any |= acc[i];

    if (any == 0u) {
        // uniform fast path: all 8 cells share one value per cascade
#pragma unroll
        for (int c = 0; c < NCASC; c++) {
            const unsigned cnt = (unsigned)s_allin[c] + ((cntThr >> (5 * c)) & 31u);
            const float cv = (float)cnt * invN;
            const float gv = (cnt > 0u) ? 0.0f : -1.0f;
            float4 g4 = make_float4(gv, gv, gv, gv);
            float4 c4v = make_float4(cv, cv, cv, cv);
            ((float4*)pg)[0] = g4; ((float4*)pg)[1] = g4;
            ((float4*)pc)[0] = c4v; ((float4*)pc)[1] = c4v;
            pg += G3; pc += G3;
        }
    } else {
#pragma unroll
        for (int c = 0; c < NCASC; c++) {
            const unsigned allc = (unsigned)s_allin[c] + ((cntThr >> (5 * c)) & 31u);
            float gv[8], cv[8];
#pragma unroll
            for (int cell = 0; cell < 8; cell++) {
                unsigned cnt   = ((acc[cell] >> (5 * c)) & 31u) + allc;
                unsigned nearf = (acc[cell] >> (25 + c)) & 1u;
                cv[cell] = (float)cnt * invN;
                gv[cell] = (cnt > 0u && nearf == 0u) ? 0.0f : -1.0f;
            }
            ((float4*)pg)[0] = make_float4(gv[0], gv[1], gv[2], gv[3]);
            ((float4*)pg)[1] = make_float4(gv[4], gv[5], gv[6], gv[7]);
            ((float4*)pc)[0] = make_float4(cv[0], cv[1], cv[2], cv[3]);
            ((float4*)pc)[1] = make_float4(cv[4], cv[5], cv[6], cv[7]);
            pg += G3; pc += G3;
        }
    }
}

extern "C" void kernel_launch(void* const* d_in, const int* in_sizes, int n_in,
                              void* d_out, int out_size)
{
    const float* K     = (const float*)d_in[0];
    const float* poses = (const float*)d_in[1];
    const int*   sc    = (const int*)d_in[3];
    const int*   wp    = (const int*)d_in[4];
    const int*   hp    = (const int*)d_in[5];

    int n_cams = in_sizes[1] / 12;
    if (n_cams > MAXCAMS) n_cams = MAXCAMS;

    const int blocks = G3 / (int)CELLS_PER_CTA;  // 2048
    grid_kernel<<<blocks, NTHREADS>>>((float*)d_out, K, poses, sc, wp, hp, n_cams);
}